// round 4
// baseline (speedup 1.0000x reference)
#include <cuda_runtime.h>

// Problem constants
#define BB   1024
#define TT   512
#define II   100
#define IIP  104    // padded input dim (2 chunks of 52, mult of 4)
#define HH   150
#define HP   160    // padded hidden (mult of 32)
#define OO   3

// rnn kernel geometry
#define K4   152    // padded K (4 chunks of 38)
#define KC   38     // k-chunk per quarter
#define HROW 12     // hs row stride (16B-aligned, rows 7..11 pad/zero)
#define RB   7      // batch rows per rnn CTA (147 CTAs cover 1024)

// Output tuple layout: out, hidden, logits
#define HID_OFF  ((size_t)BB * TT * OO)
#define LOG_OFF  (HID_OFF + (size_t)BB * TT * HH)

// Scratch: input projection xw[bt][HP] (~335 MB)
__device__ float g_xw[(size_t)BB * TT * HP];

// ---------------------------------------------------------------------------
// Kernel 1: xw[bt][j] = sum_i x[bt][i] * W_ih[j][i].
// 320 threads = (j in [0,160), kc in {0,1}); each thread holds 52 W_ih
// weights in REGISTERS. x tile (16 rows) staged row-major in smem; inner
// loop is broadcast LDS.128 + FFMA only. 2-way psum reduction per tile.
// ---------------------------------------------------------------------------
__global__ void __launch_bounds__(320, 2) xw_kernel(const float* __restrict__ x,
                                                    const float* __restrict__ W_ih) {
    __shared__ __align__(16) float xs[16 * IIP];   // [r][i]
    __shared__ float psum[2 * 16 * HP];            // [kc][r][j]
    const int tid = threadIdx.x;
    const int j  = tid % HP;
    const int kc = tid / HP;

    // one-time: weights into registers (zero-padded)
    float4 w4[13];
#pragma unroll
    for (int q = 0; q < 13; q++) {
        const int i0 = 52 * kc + 4 * q;
        float a = 0.f, b = 0.f, c = 0.f, d = 0.f;
        if (j < HH) {
            if (i0 + 0 < II) a = W_ih[j * II + i0 + 0];
            if (i0 + 1 < II) b = W_ih[j * II + i0 + 1];
            if (i0 + 2 < II) c = W_ih[j * II + i0 + 2];
            if (i0 + 3 < II) d = W_ih[j * II + i0 + 3];
        }
        w4[q] = make_float4(a, b, c, d);
    }

    const int nTiles = (BB * TT) / 16;
    for (int tile = blockIdx.x; tile < nTiles; tile += gridDim.x) {
        const int bt0 = tile * 16;
        __syncthreads();   // xs/psum reuse guard
        for (int idx = tid; idx < 16 * IIP; idx += 320) {
            const int r = idx / IIP, i = idx - r * IIP;
            xs[idx] = (i < II) ? x[(size_t)(bt0 + r) * II + i] : 0.f;
        }
        __syncthreads();

        float acc[16];
#pragma unroll
        for (int r = 0; r < 16; r++) acc[r] = 0.f;

#pragma unroll
        for (int q = 0; q < 13; q++) {
            const int i0 = 52 * kc + 4 * q;
            const float4 w = w4[q];
#pragma unroll
            for (int r = 0; r < 16; r++) {
                const float4 xv = *(const float4*)&xs[r * IIP + i0];  // broadcast
                acc[r] = fmaf(w.x, xv.x, acc[r]);
                acc[r] = fmaf(w.y, xv.y, acc[r]);
                acc[r] = fmaf(w.z, xv.z, acc[r]);
                acc[r] = fmaf(w.w, xv.w, acc[r]);
            }
        }

        float* ps = psum + kc * (16 * HP) + j;
#pragma unroll
        for (int r = 0; r < 16; r++) ps[r * HP] = acc[r];
        __syncthreads();

        // each thread reduces 8 (row, j) sums: rows 8*kc .. 8*kc+7
#pragma unroll
        for (int u = 0; u < 8; u++) {
            const int r = 8 * kc + u;
            const float s = psum[0 * (16 * HP) + r * HP + j]
                          + psum[1 * (16 * HP) + r * HP + j];
            g_xw[(size_t)(bt0 + r) * HP + j] = s;
        }
    }
}

// ---------------------------------------------------------------------------
// Kernel 2: sequential RNN. 147 CTAs x 7 batch rows (fills all SMs),
// 640 threads (20 warps, 5/5/5/5 SMSP balance). Thread=(j,kc) holds
// W_hh[j][38kc..+37] in registers. h transposed hs[k][row]; one broadcast
// LDS.128 pair feeds 7 rows. Cross-kc reduction via smem psum.
// ---------------------------------------------------------------------------
__global__ void __launch_bounds__(640, 1) rnn_kernel(const float* __restrict__ h0,
                                                     const float* __restrict__ W_hh,
                                                     float* __restrict__ out) {
    __shared__ __align__(16) float hs[2][K4 * HROW];   // [buf][k][row]
    __shared__ float psum[4][RB * HP];                  // [kc][r*HP+j]

    const int tid = threadIdx.x;
    const int j   = tid % HP;
    const int kc  = tid / HP;
    const int b0  = blockIdx.x * RB;
    const int nrows = (BB - b0 < RB) ? (BB - b0) : RB;

    // --- one-time: weights into registers ---
    float w[KC];
#pragma unroll
    for (int i = 0; i < KC; i++) {
        const int k = KC * kc + i;
        w[i] = (j < HH && k < HH) ? W_hh[j * HH + k] : 0.f;
    }

    // --- init hs: zero both buffers, fill valid rows of h0 (transposed) ---
    for (int idx = tid; idx < 2 * K4 * HROW; idx += 640) ((float*)hs)[idx] = 0.f;
    __syncthreads();
    for (int idx = tid; idx < HH * nrows; idx += 640) {
        const int k = idx / nrows, r = idx - k * nrows;
        hs[0][k * HROW + r] = h0[(b0 + r) * HH + k];
    }
    __syncthreads();

    // reduction rows for this thread: r_lo = kc (0..3), r_hi = kc+4 (4..6)
    const int r_lo = kc;
    const int r_hi = kc + 4;
    const bool v_lo = (r_lo < nrows);
    const bool v_hi = (kc < 3) && (r_hi < nrows);
    const int row_lo = v_lo ? r_lo : 0;   // clamp for safe addressing
    const int row_hi = v_hi ? r_hi : 0;
    const float* px0 = g_xw + ((size_t)(b0 + row_lo) * TT) * HP + j;
    const float* px1 = g_xw + ((size_t)(b0 + row_hi) * TT) * HP + j;
    float xw0 = px0[0];
    float xw1 = px1[0];

    float* hid_out = out + HID_OFF;
    int cur = 0;

    for (int t = 0; t < TT; t++) {
        // prefetch next step's xw (latency hidden by FMA loop)
        float nx0 = 0.f, nx1 = 0.f;
        if (t + 1 < TT) { nx0 = px0[HP]; nx1 = px1[HP]; }

        // --- main FMA loop: 7 rows x 38 k, weights in regs, h broadcast ---
        const float* hc = &hs[cur][(KC * kc) * HROW];
        float a0 = 0.f, a1 = 0.f, a2 = 0.f, a3 = 0.f;
        float a4 = 0.f, a5 = 0.f, a6 = 0.f;
#pragma unroll
        for (int i = 0; i < KC; i++) {
            const float4 va = *(const float4*)(hc + i * HROW);
            const float4 vb = *(const float4*)(hc + i * HROW + 4);
            a0 = fmaf(w[i], va.x, a0);
            a1 = fmaf(w[i], va.y, a1);
            a2 = fmaf(w[i], va.z, a2);
            a3 = fmaf(w[i], va.w, a3);
            a4 = fmaf(w[i], vb.x, a4);
            a5 = fmaf(w[i], vb.y, a5);
            a6 = fmaf(w[i], vb.z, a6);
        }

        // --- write partials ---
        float* ps = psum[kc] + j;
        ps[0 * HP] = a0; ps[1 * HP] = a1; ps[2 * HP] = a2; ps[3 * HP] = a3;
        ps[4 * HP] = a4; ps[5 * HP] = a5; ps[6 * HP] = a6;
        __syncthreads();

        // --- reduce this thread's rows across 4 kc partials + xw, relu ---
        float s0 = psum[0][r_lo * HP + j] + psum[1][r_lo * HP + j]
                 + psum[2][r_lo * HP + j] + psum[3][r_lo * HP + j] + xw0;
        s0 = fmaxf(s0, 0.f);
        float s1 = 0.f;
        if (kc < 3) {
            s1 = psum[0][r_hi * HP + j] + psum[1][r_hi * HP + j]
               + psum[2][r_hi * HP + j] + psum[3][r_hi * HP + j] + xw1;
            s1 = fmaxf(s1, 0.f);
        }

        // --- write next h state (transposed) + hidden output ---
        float* hn = hs[cur ^ 1];
        if (j < HH) {
            if (v_lo) {
                hn[j * HROW + r_lo] = s0;
                hid_out[((size_t)(b0 + r_lo) * TT + t) * HH + j] = s0;
            }
            if (v_hi) {
                hn[j * HROW + r_hi] = s1;
                hid_out[((size_t)(b0 + r_hi) * TT + t) * HH + j] = s1;
            }
        }

        xw0 = nx0; xw1 = nx1;
        px0 += HP; px1 += HP;
        __syncthreads();
        cur ^= 1;
    }
}

// ---------------------------------------------------------------------------
// Kernel 3: logits = hidden @ W_fc^T; out = one_hot(argmax(logits+g)).
// ---------------------------------------------------------------------------
__global__ void __launch_bounds__(256) post_kernel(const float* __restrict__ g,
                                                   const float* __restrict__ W_fc,
                                                   float* __restrict__ out) {
    __shared__ float wfc[OO * HP];
    const int tid = threadIdx.x;
    for (int i = tid; i < OO * HP; i += 256) {
        const int o = i / HP, k = i - o * HP;
        wfc[i] = (k < HH) ? W_fc[o * HH + k] : 0.f;
    }
    __syncthreads();

    const int warp = tid >> 5, lane = tid & 31;
    const size_t bt = (size_t)blockIdx.x * 8 + warp;
    const float* hid = out + HID_OFF + bt * HH;

    float hv[5];
#pragma unroll
    for (int m = 0; m < 5; m++) {
        const int k = lane + 32 * m;
        hv[m] = (k < HH) ? hid[k] : 0.f;
    }
    float p[OO];
#pragma unroll
    for (int o = 0; o < OO; o++) {
        float s = 0.f;
#pragma unroll
        for (int m = 0; m < 5; m++)
            s = fmaf(hv[m], wfc[o * HP + lane + 32 * m], s);
#pragma unroll
        for (int off = 16; off > 0; off >>= 1)
            s += __shfl_xor_sync(0xffffffffu, s, off);
        p[o] = s;
    }
    if (lane == 0) {
        const float z0 = p[0] + g[bt * OO + 0];
        const float z1 = p[1] + g[bt * OO + 1];
        const float z2 = p[2] + g[bt * OO + 2];
        int idx = 0; float best = z0;
        if (z1 > best) { best = z1; idx = 1; }
        if (z2 > best) { best = z2; idx = 2; }
        float* op = out + bt * OO;
        op[0] = (idx == 0) ? 1.f : 0.f;
        op[1] = (idx == 1) ? 1.f : 0.f;
        op[2] = (idx == 2) ? 1.f : 0.f;
        float* lp = out + LOG_OFF + bt * OO;
        lp[0] = p[0]; lp[1] = p[1]; lp[2] = p[2];
    }
}

// ---------------------------------------------------------------------------
extern "C" void kernel_launch(void* const* d_in, const int* in_sizes, int n_in,
                              void* d_out, int out_size) {
    const float* x    = (const float*)d_in[0];
    const float* h0   = (const float*)d_in[1];
    const float* g    = (const float*)d_in[2];
    const float* W_ih = (const float*)d_in[3];
    const float* W_hh = (const float*)d_in[4];
    const float* W_fc = (const float*)d_in[5];
    float* out = (float*)d_out;

    xw_kernel<<<592, 320>>>(x, W_ih);
    rnn_kernel<<<(BB + RB - 1) / RB, 640>>>(h0, W_hh, out);   // 147 CTAs
    post_kernel<<<(BB * TT) / 8, 256>>>(g, W_fc, out);
}

// round 5
// speedup vs baseline: 1.1491x; 1.1491x over previous
#include <cuda_runtime.h>

// Problem constants
#define BB   1024
#define TT   512
#define II   100
#define IIP  104    // padded input dim (mult of 4)
#define HH   150
#define HP   160    // padded hidden (mult of 32)
#define OO   3
#define WP   161    // weight smem pitch (conflict-free transpose fill)
#define XT   32     // xw rows per tile

// rnn kernel geometry
#define K4   152    // padded K (4 chunks of 38)
#define KC   38     // k-chunk per quarter
#define HROW 12     // hs row stride (16B-aligned)
#define RB   7      // batch rows per rnn CTA (147 CTAs)

// Output tuple layout: out, hidden, logits
#define HID_OFF  ((size_t)BB * TT * OO)
#define LOG_OFF  (HID_OFF + (size_t)BB * TT * HH)

// Scratch: input projection xw[bt][HP] (~335 MB)
__device__ float g_xw[(size_t)BB * TT * HP];

// ---------------------------------------------------------------------------
// Kernel 1: xw[bt][j] = sum_i x[bt][i] * W_ih[j][i].
// 32-row tiles. 320 threads = (jp in [0,80), half in [0,4)): each thread
// computes 2 j's (jp, jp+80) x 8 rows -> 64 FMA per 16 LDS wavefronts per
// 4-k quad (2x the FMA/LDS ratio of the R1 design, same occupancy class).
// ---------------------------------------------------------------------------
__global__ void __launch_bounds__(320, 2) xw_kernel(const float* __restrict__ x,
                                                    const float* __restrict__ W_ih) {
    extern __shared__ float sm[];
    float* WihT = sm;                 // [II][WP]
    float* xs   = sm + II * WP;       // [XT][IIP]
    const int tid = threadIdx.x;

    for (int i = tid; i < II * WP; i += 320) WihT[i] = 0.f;
    __syncthreads();
    for (int idx = tid; idx < HH * II; idx += 320) {
        const int h = idx / II, i = idx - h * II;
        WihT[i * WP + h] = W_ih[idx];
    }

    const int jp   = tid % 80;        // j pair: {jp, jp+80}
    const int half = tid / 80;        // row group: rows half*8 .. half*8+7
    const int nTiles = (BB * TT) / XT;

    for (int tile = blockIdx.x; tile < nTiles; tile += gridDim.x) {
        const int bt0 = tile * XT;
        __syncthreads();   // xs reuse guard (also covers weight fill, iter 0)
        for (int idx = tid; idx < XT * IIP; idx += 320) {
            const int r = idx / IIP, i = idx - r * IIP;
            xs[idx] = (i < II) ? x[(size_t)(bt0 + r) * II + i] : 0.f;
        }
        __syncthreads();

        float acc0[8], acc1[8];
#pragma unroll
        for (int r = 0; r < 8; r++) { acc0[r] = 0.f; acc1[r] = 0.f; }

        const float* xrow = xs + half * 8 * IIP;
#pragma unroll
        for (int kq = 0; kq < II / 4; kq++) {
            const float wa0 = WihT[(4 * kq + 0) * WP + jp];
            const float wa1 = WihT[(4 * kq + 1) * WP + jp];
            const float wa2 = WihT[(4 * kq + 2) * WP + jp];
            const float wa3 = WihT[(4 * kq + 3) * WP + jp];
            const float wb0 = WihT[(4 * kq + 0) * WP + jp + 80];
            const float wb1 = WihT[(4 * kq + 1) * WP + jp + 80];
            const float wb2 = WihT[(4 * kq + 2) * WP + jp + 80];
            const float wb3 = WihT[(4 * kq + 3) * WP + jp + 80];
#pragma unroll
            for (int r = 0; r < 8; r++) {
                const float4 xv = *(const float4*)&xrow[r * IIP + 4 * kq];  // broadcast
                acc0[r] = fmaf(xv.x, wa0, acc0[r]);
                acc0[r] = fmaf(xv.y, wa1, acc0[r]);
                acc0[r] = fmaf(xv.z, wa2, acc0[r]);
                acc0[r] = fmaf(xv.w, wa3, acc0[r]);
                acc1[r] = fmaf(xv.x, wb0, acc1[r]);
                acc1[r] = fmaf(xv.y, wb1, acc1[r]);
                acc1[r] = fmaf(xv.z, wb2, acc1[r]);
                acc1[r] = fmaf(xv.w, wb3, acc1[r]);
            }
        }
#pragma unroll
        for (int r = 0; r < 8; r++) {
            const size_t row = (size_t)(bt0 + half * 8 + r);
            g_xw[row * HP + jp]      = acc0[r];
            g_xw[row * HP + jp + 80] = acc1[r];
        }
    }
}

// ---------------------------------------------------------------------------
// Kernel 2: sequential RNN. 147 CTAs x 7 batch rows, 640 threads (20 warps,
// 5/5/5/5 SMSP balance). Thread=(j,kc) holds W_hh[j][38kc..+37] in registers.
// h transposed hs[k][row]; broadcast LDS.128 pair feeds 7 rows. Cross-kc
// reduction via smem psum. (Unchanged from R4 — measured equal to R3.)
// ---------------------------------------------------------------------------
__global__ void __launch_bounds__(640, 1) rnn_kernel(const float* __restrict__ h0,
                                                     const float* __restrict__ W_hh,
                                                     float* __restrict__ out) {
    __shared__ __align__(16) float hs[2][K4 * HROW];   // [buf][k][row]
    __shared__ float psum[4][RB * HP];                  // [kc][r*HP+j]

    const int tid = threadIdx.x;
    const int j   = tid % HP;
    const int kc  = tid / HP;
    const int b0  = blockIdx.x * RB;
    const int nrows = (BB - b0 < RB) ? (BB - b0) : RB;

    float w[KC];
#pragma unroll
    for (int i = 0; i < KC; i++) {
        const int k = KC * kc + i;
        w[i] = (j < HH && k < HH) ? W_hh[j * HH + k] : 0.f;
    }

    for (int idx = tid; idx < 2 * K4 * HROW; idx += 640) ((float*)hs)[idx] = 0.f;
    __syncthreads();
    for (int idx = tid; idx < HH * nrows; idx += 640) {
        const int k = idx / nrows, r = idx - k * nrows;
        hs[0][k * HROW + r] = h0[(b0 + r) * HH + k];
    }
    __syncthreads();

    const int r_lo = kc;
    const int r_hi = kc + 4;
    const bool v_lo = (r_lo < nrows);
    const bool v_hi = (kc < 3) && (r_hi < nrows);
    const int row_lo = v_lo ? r_lo : 0;
    const int row_hi = v_hi ? r_hi : 0;
    const float* px0 = g_xw + ((size_t)(b0 + row_lo) * TT) * HP + j;
    const float* px1 = g_xw + ((size_t)(b0 + row_hi) * TT) * HP + j;
    float xw0 = px0[0];
    float xw1 = px1[0];

    float* hid_out = out + HID_OFF;
    int cur = 0;

    for (int t = 0; t < TT; t++) {
        float nx0 = 0.f, nx1 = 0.f;
        if (t + 1 < TT) { nx0 = px0[HP]; nx1 = px1[HP]; }

        const float* hc = &hs[cur][(KC * kc) * HROW];
        float a0 = 0.f, a1 = 0.f, a2 = 0.f, a3 = 0.f;
        float a4 = 0.f, a5 = 0.f, a6 = 0.f;
#pragma unroll
        for (int i = 0; i < KC; i++) {
            const float4 va = *(const float4*)(hc + i * HROW);
            const float4 vb = *(const float4*)(hc + i * HROW + 4);
            a0 = fmaf(w[i], va.x, a0);
            a1 = fmaf(w[i], va.y, a1);
            a2 = fmaf(w[i], va.z, a2);
            a3 = fmaf(w[i], va.w, a3);
            a4 = fmaf(w[i], vb.x, a4);
            a5 = fmaf(w[i], vb.y, a5);
            a6 = fmaf(w[i], vb.z, a6);
        }

        float* ps = psum[kc] + j;
        ps[0 * HP] = a0; ps[1 * HP] = a1; ps[2 * HP] = a2; ps[3 * HP] = a3;
        ps[4 * HP] = a4; ps[5 * HP] = a5; ps[6 * HP] = a6;
        __syncthreads();

        float s0 = psum[0][r_lo * HP + j] + psum[1][r_lo * HP + j]
                 + psum[2][r_lo * HP + j] + psum[3][r_lo * HP + j] + xw0;
        s0 = fmaxf(s0, 0.f);
        float s1 = 0.f;
        if (kc < 3) {
            s1 = psum[0][r_hi * HP + j] + psum[1][r_hi * HP + j]
               + psum[2][r_hi * HP + j] + psum[3][r_hi * HP + j] + xw1;
            s1 = fmaxf(s1, 0.f);
        }

        float* hn = hs[cur ^ 1];
        if (j < HH) {
            if (v_lo) {
                hn[j * HROW + r_lo] = s0;
                hid_out[((size_t)(b0 + r_lo) * TT + t) * HH + j] = s0;
            }
            if (v_hi) {
                hn[j * HROW + r_hi] = s1;
                hid_out[((size_t)(b0 + r_hi) * TT + t) * HH + j] = s1;
            }
        }

        xw0 = nx0; xw1 = nx1;
        px0 += HP; px1 += HP;
        __syncthreads();
        cur ^= 1;
    }
}

// ---------------------------------------------------------------------------
// Kernel 3: logits = hidden @ W_fc^T; out = one_hot(argmax(logits+g)).
// ---------------------------------------------------------------------------
__global__ void __launch_bounds__(256) post_kernel(const float* __restrict__ g,
                                                   const float* __restrict__ W_fc,
                                                   float* __restrict__ out) {
    __shared__ float wfc[OO * HP];
    const int tid = threadIdx.x;
    for (int i = tid; i < OO * HP; i += 256) {
        const int o = i / HP, k = i - o * HP;
        wfc[i] = (k < HH) ? W_fc[o * HH + k] : 0.f;
    }
    __syncthreads();

    const int warp = tid >> 5, lane = tid & 31;
    const size_t bt = (size_t)blockIdx.x * 8 + warp;
    const float* hid = out + HID_OFF + bt * HH;

    float hv[5];
#pragma unroll
    for (int m = 0; m < 5; m++) {
        const int k = lane + 32 * m;
        hv[m] = (k < HH) ? hid[k] : 0.f;
    }
    float p[OO];
#pragma unroll
    for (int o = 0; o < OO; o++) {
        float s = 0.f;
#pragma unroll
        for (int m = 0; m < 5; m++)
            s = fmaf(hv[m], wfc[o * HP + lane + 32 * m], s);
#pragma unroll
        for (int off = 16; off > 0; off >>= 1)
            s += __shfl_xor_sync(0xffffffffu, s, off);
        p[o] = s;
    }
    if (lane == 0) {
        const float z0 = p[0] + g[bt * OO + 0];
        const float z1 = p[1] + g[bt * OO + 1];
        const float z2 = p[2] + g[bt * OO + 2];
        int idx = 0; float best = z0;
        if (z1 > best) { best = z1; idx = 1; }
        if (z2 > best) { best = z2; idx = 2; }
        float* op = out + bt * OO;
        op[0] = (idx == 0) ? 1.f : 0.f;
        op[1] = (idx == 1) ? 1.f : 0.f;
        op[2] = (idx == 2) ? 1.f : 0.f;
        float* lp = out + LOG_OFF + bt * OO;
        lp[0] = p[0]; lp[1] = p[1]; lp[2] = p[2];
    }
}

// ---------------------------------------------------------------------------
extern "C" void kernel_launch(void* const* d_in, const int* in_sizes, int n_in,
                              void* d_out, int out_size) {
    const float* x    = (const float*)d_in[0];
    const float* h0   = (const float*)d_in[1];
    const float* g    = (const float*)d_in[2];
    const float* W_ih = (const float*)d_in[3];
    const float* W_hh = (const float*)d_in[4];
    const float* W_fc = (const float*)d_in[5];
    float* out = (float*)d_out;

    const int xw_smem = (II * WP + XT * IIP) * (int)sizeof(float);   // ~77.7 KB
    cudaFuncSetAttribute(xw_kernel, cudaFuncAttributeMaxDynamicSharedMemorySize, xw_smem);

    xw_kernel<<<2048, 320, xw_smem>>>(x, W_ih);
    rnn_kernel<<<(BB + RB - 1) / RB, 640>>>(h0, W_hh, out);   // 147 CTAs
    post_kernel<<<(BB * TT) / 8, 256>>>(g, W_fc, out);
}